// round 17
// baseline (speedup 1.0000x reference)
#include <cuda_runtime.h>
#include <cstdint>

#define NMAX 100000
#define EMAX 1600000
#define DD 128

// Scratch (static device arrays; allocation is forbidden)
__device__ float g_side[(size_t)NMAX * DD];
__device__ float g_ego[(size_t)NMAX * DD];
__device__ int g_deg[NMAX];
__device__ int g_off[NMAX];
__device__ int g_cur[NMAX];
__device__ int g_blk[512];
__device__ int g_csr_src[EMAX];
__device__ float g_csr_val[EMAX];

__global__ __launch_bounds__(256) void copy_kernel(const float* __restrict__ src,
                                                   float* __restrict__ dst, int n4) {
    int i = blockIdx.x * blockDim.x + threadIdx.x;
    if (i < n4) ((float4*)dst)[i] = ((const float4*)src)[i];
}

// ------------------------- CSR build (once per capture, reused by layers)
__global__ __launch_bounds__(256) void zero_deg_kernel(int n) {
    int i = blockIdx.x * blockDim.x + threadIdx.x;
    if (i < n) g_deg[i] = 0;
}

__global__ __launch_bounds__(256) void hist_kernel(const int* __restrict__ dst, int E) {
    int i = blockIdx.x * blockDim.x + threadIdx.x;
    if (i < E) atomicAdd(&g_deg[__ldg(dst + i)], 1);
}

__global__ __launch_bounds__(256) void scan_part_kernel(int n) {
    __shared__ int sh[256];
    int i = blockIdx.x * 256 + threadIdx.x;
    int v = (i < n) ? g_deg[i] : 0;
    sh[threadIdx.x] = v;
    __syncthreads();
    int incl = v;
#pragma unroll
    for (int o = 1; o < 256; o <<= 1) {
        int t = (threadIdx.x >= o) ? sh[threadIdx.x - o] : 0;
        __syncthreads();
        incl += t;
        sh[threadIdx.x] = incl;
        __syncthreads();
    }
    if (i < n) g_off[i] = incl - v;
    if (threadIdx.x == 255) g_blk[blockIdx.x] = incl;
}

__global__ __launch_bounds__(512) void scan_blk_kernel(int nb) {
    __shared__ int sh[512];
    int t = threadIdx.x;
    int v = (t < nb) ? g_blk[t] : 0;
    sh[t] = v;
    __syncthreads();
    int incl = v;
#pragma unroll
    for (int o = 1; o < 512; o <<= 1) {
        int x = (t >= o) ? sh[t - o] : 0;
        __syncthreads();
        incl += x;
        sh[t] = incl;
        __syncthreads();
    }
    if (t < nb) g_blk[t] = incl - v;
}

__global__ __launch_bounds__(256) void scan_add_kernel(int n) {
    int i = blockIdx.x * 256 + threadIdx.x;
    if (i < n) {
        int o = g_off[i] + g_blk[blockIdx.x];
        g_off[i] = o;
        g_cur[i] = o;
    }
}

// Scatter edge payloads directly into CSR order (no eidx indirection later).
__global__ __launch_bounds__(256) void scatter_kernel(const int* __restrict__ src,
                                                      const int* __restrict__ dst,
                                                      const float* __restrict__ val,
                                                      int E) {
    int i = blockIdx.x * blockDim.x + threadIdx.x;
    if (i < E) {
        int pos = atomicAdd(&g_cur[__ldg(dst + i)], 1);
        g_csr_src[pos] = __ldg(src + i);
        g_csr_val[pos] = __ldg(val + i);
    }
}

// ------------------------- CSR SpMM: one warp per dst row, register acc.
// Contiguous (src,val) reads; 4-wide unrolled shfl-broadcast gathers.
__global__ __launch_bounds__(256) void spmm_csr_kernel(const float* __restrict__ x, int N) {
    int row = (blockIdx.x * blockDim.x + threadIdx.x) >> 5;
    int lane = threadIdx.x & 31;
    if (row >= N) return;
    int off = g_off[row];
    int deg = g_deg[row];
    float4 acc = make_float4(0.f, 0.f, 0.f, 0.f);
    for (int j0 = 0; j0 < deg; j0 += 32) {
        int myj = j0 + lane;
        int s = (myj < deg) ? __ldg(g_csr_src + off + myj) : 0;
        float v = (myj < deg) ? __ldg(g_csr_val + off + myj) : 0.f;
        int cnt = min(32, deg - j0);
        int t = 0;
        for (; t + 3 < cnt; t += 4) {
            int s0 = __shfl_sync(0xffffffffu, s, t);
            int s1 = __shfl_sync(0xffffffffu, s, t + 1);
            int s2 = __shfl_sync(0xffffffffu, s, t + 2);
            int s3 = __shfl_sync(0xffffffffu, s, t + 3);
            float v0 = __shfl_sync(0xffffffffu, v, t);
            float v1 = __shfl_sync(0xffffffffu, v, t + 1);
            float v2 = __shfl_sync(0xffffffffu, v, t + 2);
            float v3 = __shfl_sync(0xffffffffu, v, t + 3);
            float4 m0 = ((const float4*)(x + (size_t)s0 * DD))[lane];
            float4 m1 = ((const float4*)(x + (size_t)s1 * DD))[lane];
            float4 m2 = ((const float4*)(x + (size_t)s2 * DD))[lane];
            float4 m3 = ((const float4*)(x + (size_t)s3 * DD))[lane];
            acc.x += v0 * m0.x; acc.y += v0 * m0.y; acc.z += v0 * m0.z; acc.w += v0 * m0.w;
            acc.x += v1 * m1.x; acc.y += v1 * m1.y; acc.z += v1 * m1.z; acc.w += v1 * m1.w;
            acc.x += v2 * m2.x; acc.y += v2 * m2.y; acc.z += v2 * m2.z; acc.w += v2 * m2.w;
            acc.x += v3 * m3.x; acc.y += v3 * m3.y; acc.z += v3 * m3.z; acc.w += v3 * m3.w;
        }
        for (; t < cnt; t++) {
            int s0 = __shfl_sync(0xffffffffu, s, t);
            float v0 = __shfl_sync(0xffffffffu, v, t);
            float4 m0 = ((const float4*)(x + (size_t)s0 * DD))[lane];
            acc.x += v0 * m0.x; acc.y += v0 * m0.y; acc.z += v0 * m0.z; acc.w += v0 * m0.w;
        }
    }
    ((float4*)(g_side + (size_t)row * DD))[lane] = acc;
}

// ---------------- persistent fused dual tf32 GEMM layer --------------------
// 148 CTAs grid-stride over 64-row tiles; W_sum/W_prod staged in SMEM once.
//   S = (ego+side) @ W_sum;  P = (ego*side) @ W_prod
//   e = lrelu(S+b_s) + lrelu(P+b_p);  row-L2-norm
//   writes g_ego (un-normalized) and out_norm (normalized).
#define AS_WORDS 8192
#define AP_WORDS 8192
#define BS_WORDS 16384
#define GEMM_SMEM ((AS_WORDS + AP_WORDS + 2 * BS_WORDS + 64) * 4)   // ~196KB

__device__ __forceinline__ uint32_t to_tf32(float f) {
    uint32_t u;
    asm("cvt.rna.tf32.f32 %0, %1;" : "=r"(u) : "f"(f));
    return u;
}
__device__ __forceinline__ float lrelu(float x) {
    return x > 0.f ? x : 0.01f * x;
}

__global__ __launch_bounds__(256) void layer_fused_kernel(const float* __restrict__ emb,
                                                          int use_g_ego,
                                                          const float* __restrict__ W_sum,
                                                          const float* __restrict__ b_sum,
                                                          const float* __restrict__ W_prod,
                                                          const float* __restrict__ b_prod,
                                                          float* __restrict__ out_norm,
                                                          int n_rows, int n_tiles) {
    extern __shared__ uint32_t smem[];
    uint32_t* AsS = smem;
    uint32_t* AsP = smem + AS_WORDS;
    uint32_t* BsS = smem + AS_WORDS + AP_WORDS;
    uint32_t* BsP = BsS + BS_WORDS;
    float* rowsum = (float*)(BsP + BS_WORDS);        // 64 floats

    const int tid = threadIdx.x;
    const int wid = tid >> 5;
    const int lane = tid & 31;

    const float* __restrict__ ego = use_g_ego ? (const float*)g_ego : emb;

    const int col4 = tid & 31;
    const int rbase = tid >> 5;
    const int a_sw = col4 ^ rbase;
    const int b_sw = col4 ^ ((rbase & 3) << 1);

    // ---- stage both weight matrices once
#pragma unroll
    for (int j = 0; j < 16; j++) {
        int k = j * 8 + rbase;
        float4 w1 = *(const float4*)(W_sum + (size_t)k * DD + col4 * 4);
        ((uint4*)BsS)[k * 32 + b_sw] =
            make_uint4(to_tf32(w1.x), to_tf32(w1.y), to_tf32(w1.z), to_tf32(w1.w));
        float4 w2 = *(const float4*)(W_prod + (size_t)k * DD + col4 * 4);
        ((uint4*)BsP)[k * 32 + b_sw] =
            make_uint4(to_tf32(w2.x), to_tf32(w2.y), to_tf32(w2.z), to_tf32(w2.w));
    }

    const int warp_m = wid & 1;
    const int warp_n = wid >> 1;
    const int g = lane >> 2, tg = lane & 3;

    float2 bvs[4], bvp[4];
#pragma unroll
    for (int nt = 0; nt < 4; nt++) {
        bvs[nt] = *(const float2*)(b_sum + warp_n * 32 + nt * 8 + tg * 2);
        bvp[nt] = *(const float2*)(b_prod + warp_n * 32 + nt * 8 + tg * 2);
    }

    for (int t = blockIdx.x; t < n_tiles; t += gridDim.x) {
        const int row0 = t * 64;
        if (tid < 64) rowsum[tid] = 0.f;

        // ---- A fill
#pragma unroll
        for (int j = 0; j < 8; j++) {
            int row = j * 8 + rbase;
            int gr = row0 + row;
            float4 e = make_float4(0.f, 0.f, 0.f, 0.f), sd = e;
            if (gr < n_rows) {
                e = *(const float4*)(ego + (size_t)gr * DD + col4 * 4);
                sd = *(const float4*)(g_side + (size_t)gr * DD + col4 * 4);
            }
            ((uint4*)AsS)[row * 32 + a_sw] =
                make_uint4(to_tf32(e.x + sd.x), to_tf32(e.y + sd.y),
                           to_tf32(e.z + sd.z), to_tf32(e.w + sd.w));
            ((uint4*)AsP)[row * 32 + a_sw] =
                make_uint4(to_tf32(e.x * sd.x), to_tf32(e.y * sd.y),
                           to_tf32(e.z * sd.z), to_tf32(e.w * sd.w));
        }
        __syncthreads();

        // ---- compute
        float accS[2][4][4], accP[2][4][4];
#pragma unroll
        for (int mt = 0; mt < 2; mt++)
#pragma unroll
            for (int nt = 0; nt < 4; nt++)
#pragma unroll
                for (int q = 0; q < 4; q++) { accS[mt][nt][q] = 0.f; accP[mt][nt][q] = 0.f; }

#pragma unroll 2
        for (int s = 0; s < 16; s++) {
            const int c4 = s * 2;
            uint32_t aS[2][4], aP[2][4];
#pragma unroll
            for (int mt = 0; mt < 2; mt++) {
                int r0 = warp_m * 32 + mt * 16 + g;
                int i0 = (c4 ^ g) * 4, i1 = ((c4 + 1) ^ g) * 4;
                const uint32_t* loS = AsS + r0 * 128 + tg;
                const uint32_t* hiS = AsS + (r0 + 8) * 128 + tg;
                aS[mt][0] = loS[i0]; aS[mt][1] = hiS[i0];
                aS[mt][2] = loS[i1]; aS[mt][3] = hiS[i1];
                const uint32_t* loP = AsP + r0 * 128 + tg;
                const uint32_t* hiP = AsP + (r0 + 8) * 128 + tg;
                aP[mt][0] = loP[i0]; aP[mt][1] = hiP[i0];
                aP[mt][2] = loP[i1]; aP[mt][3] = hiP[i1];
            }
            const int k0 = s * 8 + tg;
            const int sw = tg << 1;
#pragma unroll
            for (int nt = 0; nt < 4; nt++) {
                int n = warp_n * 32 + nt * 8 + g;
                int idx = ((n >> 2) ^ sw) * 4 + (n & 3);
                uint32_t bS0 = BsS[k0 * 128 + idx];
                uint32_t bS1 = BsS[(k0 + 4) * 128 + idx];
                uint32_t bP0 = BsP[k0 * 128 + idx];
                uint32_t bP1 = BsP[(k0 + 4) * 128 + idx];
#pragma unroll
                for (int mt = 0; mt < 2; mt++) {
                    asm volatile(
                        "mma.sync.aligned.m16n8k8.row.col.f32.tf32.tf32.f32 "
                        "{%0,%1,%2,%3}, {%4,%5,%6,%7}, {%8,%9}, {%0,%1,%2,%3};"
                        : "+f"(accS[mt][nt][0]), "+f"(accS[mt][nt][1]),
                          "+f"(accS[mt][nt][2]), "+f"(accS[mt][nt][3])
                        : "r"(aS[mt][0]), "r"(aS[mt][1]), "r"(aS[mt][2]), "r"(aS[mt][3]),
                          "r"(bS0), "r"(bS1));
                    asm volatile(
                        "mma.sync.aligned.m16n8k8.row.col.f32.tf32.tf32.f32 "
                        "{%0,%1,%2,%3}, {%4,%5,%6,%7}, {%8,%9}, {%0,%1,%2,%3};"
                        : "+f"(accP[mt][nt][0]), "+f"(accP[mt][nt][1]),
                          "+f"(accP[mt][nt][2]), "+f"(accP[mt][nt][3])
                        : "r"(aP[mt][0]), "r"(aP[mt][1]), "r"(aP[mt][2]), "r"(aP[mt][3]),
                          "r"(bP0), "r"(bP1));
                }
            }
        }

        // ---- epilogue
#pragma unroll
        for (int mt = 0; mt < 2; mt++)
#pragma unroll
            for (int hi = 0; hi < 2; hi++) {
                int rl = warp_m * 32 + mt * 16 + hi * 8 + g;
                int grow = row0 + rl;
                if (grow < n_rows) {
                    float ps = 0.f;
#pragma unroll
                    for (int nt = 0; nt < 4; nt++) {
                        float e0 = lrelu(accS[mt][nt][hi * 2 + 0] + bvs[nt].x) +
                                   lrelu(accP[mt][nt][hi * 2 + 0] + bvp[nt].x);
                        float e1 = lrelu(accS[mt][nt][hi * 2 + 1] + bvs[nt].y) +
                                   lrelu(accP[mt][nt][hi * 2 + 1] + bvp[nt].y);
                        accS[mt][nt][hi * 2 + 0] = e0;
                        accS[mt][nt][hi * 2 + 1] = e1;
                        ps += e0 * e0 + e1 * e1;
                    }
                    atomicAdd(&rowsum[rl], ps);
                }
            }
        __syncthreads();
#pragma unroll
        for (int mt = 0; mt < 2; mt++)
#pragma unroll
            for (int hi = 0; hi < 2; hi++) {
                int rl = warp_m * 32 + mt * 16 + hi * 8 + g;
                int grow = row0 + rl;
                if (grow < n_rows) {
                    float inv = 1.f / fmaxf(sqrtf(rowsum[rl]), 1e-12f);
                    float* ep = g_ego + (size_t)grow * DD + warp_n * 32 + tg * 2;
                    float* op = out_norm + (size_t)grow * DD + warp_n * 32 + tg * 2;
#pragma unroll
                    for (int nt = 0; nt < 4; nt++) {
                        float e0 = accS[mt][nt][hi * 2 + 0];
                        float e1 = accS[mt][nt][hi * 2 + 1];
                        *(float2*)(ep + nt * 8) = make_float2(e0, e1);
                        *(float2*)(op + nt * 8) = make_float2(e0 * inv, e1 * inv);
                    }
                }
            }
        __syncthreads();
    }
}

extern "C" void kernel_launch(void* const* d_in, const int* in_sizes, int n_in,
                              void* d_out, int out_size) {
    const float* emb    = (const float*)d_in[0];
    const int*   e_src  = (const int*)d_in[1];
    const int*   e_dst  = (const int*)d_in[2];
    const float* e_val  = (const float*)d_in[3];
    const float* W_sum  = (const float*)d_in[4];
    const float* b_sum  = (const float*)d_in[5];
    const float* W_prod = (const float*)d_in[6];
    const float* b_prod = (const float*)d_in[7];
    float* out = (float*)d_out;

    const int N = in_sizes[0] / DD;
    const int E = in_sizes[1];
    const int L = in_sizes[4] / (DD * DD);

    cudaFuncSetAttribute(layer_fused_kernel,
                         cudaFuncAttributeMaxDynamicSharedMemorySize, GEMM_SMEM);

    const int n4 = N * (DD / 4);
    const int eb_blocks = (n4 + 255) / 256;
    const int nblocks = (N + 255) / 256;
    const int eblocks = (E + 255) / 256;

    copy_kernel<<<eb_blocks, 256>>>(emb, out, n4);

    // CSR build (reused by both layers)
    zero_deg_kernel<<<nblocks, 256>>>(N);
    hist_kernel<<<eblocks, 256>>>(e_dst, E);
    scan_part_kernel<<<nblocks, 256>>>(N);
    scan_blk_kernel<<<1, 512>>>(nblocks);
    scan_add_kernel<<<nblocks, 256>>>(N);
    scatter_kernel<<<eblocks, 256>>>(e_src, e_dst, e_val, E);

    const int spmm_blocks = (N + 7) / 8;
    const int n_tiles = (N + 63) / 64;
    const int pers_grid = 148;

    for (int i = 0; i < L; i++) {
        // layer 0 SpMM reads emb directly (== out[0], removes copy dependency)
        const float* x = (i == 0) ? emb : out + (size_t)i * N * DD;
        spmm_csr_kernel<<<spmm_blocks, 256>>>(x, N);
        layer_fused_kernel<<<pers_grid, 256, GEMM_SMEM>>>(
            emb, (i == 0) ? 0 : 1,
            W_sum + (size_t)i * DD * DD, b_sum + (size_t)i * DD,
            W_prod + (size_t)i * DD * DD, b_prod + (size_t)i * DD,
            out + (size_t)(i + 1) * N * DD, N, n_tiles);
    }
}